// round 10
// baseline (speedup 1.0000x reference)
#include <cuda_runtime.h>

#define EPS 1e-5f

typedef unsigned long long u64;

// ---------------- f32x2 helpers ----------------
__device__ __forceinline__ void fma2(u64& d, u64 a, u64 b) {
    asm volatile("fma.rn.f32x2 %0, %1, %2, %0;" : "+l"(d) : "l"(a), "l"(b));
}
__device__ __forceinline__ u64 dup2(float x) {
    u64 r; asm("mov.b64 %0, {%1, %1};" : "=l"(r) : "f"(x)); return r;
}
__device__ __forceinline__ float2 unpack2(u64 v) {
    float2 r; asm("mov.b64 {%0, %1}, %2;" : "=f"(r.x), "=f"(r.y) : "l"(v)); return r;
}

// ---------------- scratch (device globals; no allocation allowed) ----------------
__device__ float g_xn[4 * 144 * 4096];        // normalized input
__device__ float g_wint[144 * 64];            // w_in transposed [c][o]
__device__ float g_w1oc[9 * 64 * 64];         // w1 as [drds][o][c]
__device__ float g_w2tt[64 * 576];            // w2 as [o3][rs*64+o2]
__device__ float g_sin[64], g_tin[64];
__device__ float g_s1[64],  g_t1[64];
__device__ float g_s2[64],  g_t2[64];
__device__ float g_sout[144], g_tout[144];
__device__ float g_A[16384 * 25 * 64];        // post GEMM1+BN+ReLU  [pos][k][o]
__device__ float g_A1[16384 * 9 * 64];        // post conv1+BN+ReLU  [pos][rs][o2]
__device__ float g_B2[16384 * 64];            // post conv2+BN+ReLU  [pos][o3]

// ---------------- weight transpose + BN folding ----------------
__global__ void prep_kernel(const float* __restrict__ w_in,
                            const float* __restrict__ gin, const float* __restrict__ bin,
                            const float* __restrict__ min_, const float* __restrict__ vin,
                            const float* __restrict__ w1,
                            const float* __restrict__ g1, const float* __restrict__ b1,
                            const float* __restrict__ m1, const float* __restrict__ v1,
                            const float* __restrict__ w2,
                            const float* __restrict__ g2, const float* __restrict__ b2,
                            const float* __restrict__ m2, const float* __restrict__ v2,
                            const float* __restrict__ go, const float* __restrict__ bo,
                            const float* __restrict__ mo, const float* __restrict__ vo)
{
    int i = blockIdx.x * blockDim.x + threadIdx.x;   // grid covers 36864
    if (i < 36864) {
        // w1oc[drds][o][c] = w1[c][o][drds]
        int drds = i >> 12; int r1 = i & 4095;
        int o = r1 >> 6; int c = r1 & 63;
        g_w1oc[i] = w1[(c * 64 + o) * 9 + drds];
        // w2tt[o3][rs*64+o2] = w2[o3][o2][rs]
        int o3 = i / 576; int r2 = i - o3 * 576;
        int rs = r2 >> 6; int o2b = r2 & 63;
        g_w2tt[i] = w2[(o3 * 64 + o2b) * 9 + rs];
    }
    if (i < 9216) { int c = i >> 6; int o = i & 63; g_wint[i] = w_in[o * 144 + c]; }
    if (i < 64) {
        float s;
        s = gin[i] * rsqrtf(vin[i] + EPS); g_sin[i] = s; g_tin[i] = bin[i] - min_[i] * s;
        s = g1[i]  * rsqrtf(v1[i]  + EPS); g_s1[i]  = s; g_t1[i]  = b1[i]  - m1[i]  * s;
        s = g2[i]  * rsqrtf(v2[i]  + EPS); g_s2[i]  = s; g_t2[i]  = b2[i]  - m2[i]  * s;
    }
    if (i < 144) {
        float s = go[i] * rsqrtf(vo[i] + EPS); g_sout[i] = s; g_tout[i] = bo[i] - mo[i] * s;
    }
}

// ---------------- L2 normalize over channels ----------------
__global__ void normalize_kernel(const float* __restrict__ x)
{
    int p = blockIdx.x * 256 + threadIdx.x;          // 16384 positions
    int b = p >> 12, hw = p & 4095;
    const float* xb = x + (size_t)b * 589824 + hw;   // 144*4096
    float ss = 0.f;
    #pragma unroll 4
    for (int c = 0; c < 144; c++) { float v = xb[c * 4096]; ss += v * v; }
    float inv = 1.0f / fmaxf(sqrtf(ss), 1e-12f);
    float* yb = g_xn + (size_t)b * 589824 + hw;
    #pragma unroll 4
    for (int c = 0; c < 144; c++) yb[c * 4096] = xb[c * 4096] * inv;
}

// ---------------- GEMM1 (mirror-symmetric): only k=12..24 computed ----------------
// z[o,k,p] = sum_c w[o,c]*xn[c,p+dk]*xn[c,p]  is symmetric under
// (p,k) <-> (p+dk, 24-k); BN+ReLU elementwise => A[p][k] = A[p+dk][24-k].
__global__ void __launch_bounds__(256) gemm1_kernel()
{
    extern __shared__ float sm[];
    float* y   = sm;                                 // 7488
    float* wsm = sm + 7488;                          // 9216
    int pos0 = blockIdx.x << 2;
    int b = pos0 >> 12, hw0 = pos0 & 4095;
    int h0 = hw0 >> 6, w0 = hw0 & 63;
    int tid = threadIdx.x;
    const float* xb = g_xn + (size_t)b * 589824;

    // stage w_in^T  [c][o]
    #pragma unroll
    for (int j = 0; j < 9; j++) {
        int idx = tid + j * 256;                     // 2304 float4 = 9216 floats
        ((float4*)wsm)[idx] = ((const float4*)g_wint)[idx];
    }
    // build y tile for k=12..24: y[(c*13 + (k-12))*4 + p]
    for (int u = tid; u < 1872; u += 256) {
        int c = u / 13, kt = u - c * 13;
        int k = kt + 12;
        int kh = k / 5, kw = k - kh * 5;
        int gh = h0 + kh - 2;
        bool rok = ((unsigned)gh < 64u);
        const float* xc = xb + c * 4096;
        float4 out;
        float ctr0 = xc[(h0 << 6) + w0 + 0], ctr1 = xc[(h0 << 6) + w0 + 1];
        float ctr2 = xc[(h0 << 6) + w0 + 2], ctr3 = xc[(h0 << 6) + w0 + 3];
        int gw0 = w0 + kw - 2;
        float v0 = (rok && (unsigned)(gw0 + 0) < 64u) ? xc[(gh << 6) + gw0 + 0] : 0.f;
        float v1 = (rok && (unsigned)(gw0 + 1) < 64u) ? xc[(gh << 6) + gw0 + 1] : 0.f;
        float v2 = (rok && (unsigned)(gw0 + 2) < 64u) ? xc[(gh << 6) + gw0 + 2] : 0.f;
        float v3 = (rok && (unsigned)(gw0 + 3) < 64u) ? xc[(gh << 6) + gw0 + 3] : 0.f;
        out.x = v0 * ctr0; out.y = v1 * ctr1; out.z = v2 * ctr2; out.w = v3 * ctr3;
        ((float4*)y)[u] = out;
    }
    __syncthreads();

    int lane = tid & 31, g = tid >> 5;
    int oc = lane & 15;                              // channels 4oc..4oc+3
    int h  = lane >> 4;                              // c-parity half
    int nk = (g < 5) ? 2 : 1;                        // k = 12 + g + 8*kk
    u64 acc[2][4][2];                                // [kk][ch][pair]
    #pragma unroll
    for (int kk = 0; kk < 2; kk++)
        #pragma unroll
        for (int j = 0; j < 4; j++) { acc[kk][j][0] = 0; acc[kk][j][1] = 0; }

    const float* wrow = wsm + (h << 6) + (oc << 2);  // + ci*128
    const float* yrow = y + ((h * 13 + g) << 2);     // + ci*104, + kk*32

    #pragma unroll 2
    for (int ci = 0; ci < 72; ci++) {
        float4 w4 = *(const float4*)(wrow + (ci << 7));
        u64 wd0 = dup2(w4.x), wd1 = dup2(w4.y), wd2 = dup2(w4.z), wd3 = dup2(w4.w);
        const float* yc = yrow + ci * 104;
        #pragma unroll
        for (int kk = 0; kk < 2; kk++) {
            if (kk < nk) {
                ulonglong2 yv = *(const ulonglong2*)(yc + (kk << 5));
                fma2(acc[kk][0][0], yv.x, wd0); fma2(acc[kk][0][1], yv.y, wd0);
                fma2(acc[kk][1][0], yv.x, wd1); fma2(acc[kk][1][1], yv.y, wd1);
                fma2(acc[kk][2][0], yv.x, wd2); fma2(acc[kk][2][1], yv.y, wd2);
                fma2(acc[kk][3][0], yv.x, wd3); fma2(acc[kk][3][1], yv.y, wd3);
            }
        }
    }

    // epilogue: reduce across c-halves; write self slot, mirror-partner slot,
    // and the OOB-partner constant relu(t).
    float4 s4 = *(const float4*)&g_sin[oc << 2];
    float4 t4 = *(const float4*)&g_tin[oc << 2];
    float4 cst;
    cst.x = fmaxf(t4.x, 0.f); cst.y = fmaxf(t4.y, 0.f);
    cst.z = fmaxf(t4.z, 0.f); cst.w = fmaxf(t4.w, 0.f);

    #pragma unroll
    for (int kk = 0; kk < 2; kk++) {
        if (kk < nk) {
            int k = 12 + g + (kk << 3);
            float2 sel[4];
            #pragma unroll
            for (int j = 0; j < 4; j++) {
                u64 p0 = acc[kk][j][0], p1 = acc[kk][j][1];
                u64 q0 = __shfl_xor_sync(0xffffffffu, p0, 16);
                u64 q1 = __shfl_xor_sync(0xffffffffu, p1, 16);
                float2 a0 = unpack2(p0), b0 = unpack2(q0);
                float2 a1 = unpack2(p1), b1 = unpack2(q1);
                float2 s0 = make_float2(a0.x + b0.x, a0.y + b0.y);
                float2 s1 = make_float2(a1.x + b1.x, a1.y + b1.y);
                sel[j] = h ? s1 : s0;
            }
            float4 r[2];
            r[0].x = fmaxf(sel[0].x * s4.x + t4.x, 0.f);
            r[0].y = fmaxf(sel[1].x * s4.y + t4.y, 0.f);
            r[0].z = fmaxf(sel[2].x * s4.z + t4.z, 0.f);
            r[0].w = fmaxf(sel[3].x * s4.w + t4.w, 0.f);
            r[1].x = fmaxf(sel[0].y * s4.x + t4.x, 0.f);
            r[1].y = fmaxf(sel[1].y * s4.y + t4.y, 0.f);
            r[1].z = fmaxf(sel[2].y * s4.z + t4.z, 0.f);
            r[1].w = fmaxf(sel[3].y * s4.w + t4.w, 0.f);

            int kh = k / 5, kw = k - kh * 5;
            int dh = kh - 2, dw = kw - 2;
            int mk = 24 - k;
            #pragma unroll
            for (int e = 0; e < 2; e++) {
                int poff = (h << 1) + e;
                int p = pos0 + poff;
                *(float4*)&g_A[(((size_t)p * 25 + k) << 6) + (oc << 2)] = r[e];
                if (k != 12) {
                    int ww = w0 + poff;
                    int qh = h0 + dh, qw = ww + dw;
                    if ((unsigned)qh < 64u && (unsigned)qw < 64u) {
                        int q = (b << 12) + (qh << 6) + qw;
                        *(float4*)&g_A[(((size_t)q * 25 + mk) << 6) + (oc << 2)] = r[e];
                    }
                    int rh = h0 - dh, rw = ww - dw;
                    if (!((unsigned)rh < 64u && (unsigned)rw < 64u)) {
                        *(float4*)&g_A[(((size_t)p * 25 + mk) << 6) + (oc << 2)] = cst;
                    }
                }
            }
        }
    }
}

// ---------------- Conv1: 3x3 VALID over 5x5 grid, 64->64; BN+ReLU ----------------
// CTA = 8 positions (4 position-pairs q). smem: As interleaved [q][k][opair][4]
// only (51.5KB) -> 3 CTA/SM. Weights read directly from g_w1oc via coalesced
// LDG.128 (147KB, L1-resident: smem carveout leaves ~176KB L1D and L1 persists
// across CTAs within the launch). No per-drds staging, no inner barriers.
__global__ void __launch_bounds__(256, 3) conv1_kernel()
{
    extern __shared__ float sm[];
    float* As = sm;                                  // 4 * 3216 = 12864
    int pos0 = blockIdx.x << 3;
    int tid = threadIdx.x;

    // stage As: As[q*3216 + k*128 + op*4 + {o0p0,o0p1,o1p0,o1p1}]
    for (int u = tid; u < 3200; u += 256) {
        int pq = u / 800;
        int rem = u - pq * 800;
        int k = rem >> 5, op = rem & 31;
        const float* src = g_A + (((size_t)(pos0 + 2 * pq) * 25 + k) << 6) + (op << 1);
        float2 v0 = *(const float2*)src;             // pos 2pq   (o, o+1)
        float2 v1 = *(const float2*)(src + 1600);    // pos 2pq+1 (o, o+1)
        *(float4*)&As[pq * 3216 + (k << 7) + (op << 2)] = make_float4(v0.x, v1.x, v0.y, v1.y);
    }
    __syncthreads();

    int lane = tid & 31, g = tid >> 5;
    int oc = lane & 15;
    int q = g & 3;
    int quarter = ((g >> 2) << 1) + (lane >> 4);     // 0..3
    int rs0 = (quarter == 0) ? 0 : 2 * quarter + 1;  // 0,3,5,7
    int nrs = (quarter == 0) ? 3 : 2;
    int roff[3];
    #pragma unroll
    for (int i = 0; i < 3; i++) {
        int rs = rs0 + i;
        roff[i] = (rs / 3) * 5 + rs % 3;
    }

    u64 acc[3][4];
    #pragma unroll
    for (int i = 0; i < 3; i++)
        #pragma unroll
        for (int j = 0; j < 4; j++) acc[i][j] = 0;

    const float* wbase = g_w1oc + (oc << 2);

    for (int drds = 0; drds < 9; drds++) {
        int dr = drds / 3, ds = drds - dr * 3;
        int shift = dr * 5 + ds;
        int base[3];
        #pragma unroll
        for (int i = 0; i < 3; i++)
            base[i] = q * 3216 + ((roff[i] + shift) << 7);

        const float* wrow = wbase + (drds << 12);
        #pragma unroll 2
        for (int op = 0; op < 32; op++) {
            float4 we = __ldg((const float4*)(wrow + (op << 7)));       // o = 2op
            float4 wo = __ldg((const float4*)(wrow + (op << 7) + 64));  // o = 2op+1
            u64 we0 = dup2(we.x), we1 = dup2(we.y), we2 = dup2(we.z), we3 = dup2(we.w);
            u64 wo0 = dup2(wo.x), wo1 = dup2(wo.y), wo2 = dup2(wo.z), wo3 = dup2(wo.w);
            #pragma unroll
            for (int i = 0; i < 3; i++) {
                if (i < nrs) {
                    ulonglong2 a = *(const ulonglong2*)&As[base[i] + (op << 2)];
                    fma2(acc[i][0], a.x, we0); fma2(acc[i][1], a.x, we1);
                    fma2(acc[i][2], a.x, we2); fma2(acc[i][3], a.x, we3);
                    fma2(acc[i][0], a.y, wo0); fma2(acc[i][1], a.y, wo1);
                    fma2(acc[i][2], a.y, wo2); fma2(acc[i][3], a.y, wo3);
                }
            }
        }
    }

    float4 s4 = *(const float4*)&g_s1[oc << 2];
    float4 t4 = *(const float4*)&g_t1[oc << 2];
    #pragma unroll
    for (int i = 0; i < 3; i++) {
        if (i < nrs) {
            int rs = rs0 + i;
            float2 v0 = unpack2(acc[i][0]);
            float2 v1 = unpack2(acc[i][1]);
            float2 v2 = unpack2(acc[i][2]);
            float2 v3 = unpack2(acc[i][3]);
            float4 r0, r1;
            r0.x = fmaxf(v0.x * s4.x + t4.x, 0.f);
            r0.y = fmaxf(v1.x * s4.y + t4.y, 0.f);
            r0.z = fmaxf(v2.x * s4.z + t4.z, 0.f);
            r0.w = fmaxf(v3.x * s4.w + t4.w, 0.f);
            r1.x = fmaxf(v0.y * s4.x + t4.x, 0.f);
            r1.y = fmaxf(v1.y * s4.y + t4.y, 0.f);
            r1.z = fmaxf(v2.y * s4.z + t4.z, 0.f);
            r1.w = fmaxf(v3.y * s4.w + t4.w, 0.f);
            *(float4*)&g_A1[(((size_t)(pos0 + 2 * q)     * 9 + rs) << 6) + (oc << 2)] = r0;
            *(float4*)&g_A1[(((size_t)(pos0 + 2 * q + 1) * 9 + rs) << 6) + (oc << 2)] = r1;
        }
    }
}

// ---------------- Conv2: 3x3 -> 1x1, 64->64; BN+ReLU ----------------
// CTA = 32 positions. smem: A1[32][576] (73.7KB) + w chunk [64][68] (17.4KB) -> 2 CTA/SM.
__global__ void __launch_bounds__(256) conv2_kernel()
{
    extern __shared__ float sm[];
    float* A1s = sm;                                 // 18432
    float* ws2 = sm + 18432;                         // 4352
    int pos0 = blockIdx.x << 5;
    int tid = threadIdx.x;

    const float4* src = (const float4*)(g_A1 + ((size_t)pos0 * 576));
    for (int i = tid; i < 4608; i += 256) ((float4*)A1s)[i] = src[i];

    int o3b = tid & 31, g = tid >> 5;                // warp g owns p = g+8i
    u64 acc[4][2];
    #pragma unroll
    for (int i = 0; i < 4; i++) { acc[i][0] = 0; acc[i][1] = 0; }

    for (int jc = 0; jc < 9; jc++) {
        __syncthreads();
        #pragma unroll
        for (int j2 = 0; j2 < 16; j2++) {
            int idx = tid + (j2 << 8);
            ws2[(idx >> 6) * 68 + (idx & 63)] = g_w2tt[(idx >> 6) * 576 + (jc << 6) + (idx & 63)];
        }
        __syncthreads();

        int jbase = jc << 6;
        for (int jj = 0; jj < 64; jj += 4) {
            ulonglong2 wlo = *(const ulonglong2*)&ws2[o3b * 68 + jj];
            ulonglong2 whi = *(const ulonglong2*)&ws2[(o3b + 32) * 68 + jj];
            #pragma unroll
            for (int i = 0; i < 4; i++) {
                int p = g + (i << 3);
                ulonglong2 a = *(const ulonglong2*)&A1s[p * 576 + jbase + jj];
                fma2(acc[i][0], a.x, wlo.x);
                fma2(acc[i][0], a.y, wlo.y);
                fma2(acc[i][1], a.x, whi.x);
                fma2(acc[i][1], a.y, whi.y);
            }
        }
    }

    float sa = g_s2[o3b], ta = g_t2[o3b], sb = g_s2[o3b + 32], tb = g_t2[o3b + 32];
    #pragma unroll
    for (int i = 0; i < 4; i++) {
        int p = pos0 + g + (i << 3);
        float2 va = unpack2(acc[i][0]);
        float2 vb = unpack2(acc[i][1]);
        g_B2[(p << 6) + o3b]      = fmaxf((va.x + va.y) * sa + ta, 0.f);
        g_B2[(p << 6) + o3b + 32] = fmaxf((vb.x + vb.y) * sb + tb, 0.f);
    }
}

// ---------------- GEMM out: 64->144, BN (no ReLU) ----------------
__global__ void __launch_bounds__(256) gemmout_kernel(const float* __restrict__ w_out,
                                                      float* __restrict__ out)
{
    extern __shared__ float sm[];                    // 4160 + 9216 floats
    float* B2t = sm;
    float* ws  = sm + 4160;
    int pos0 = blockIdx.x << 6;
    int tid = threadIdx.x;

    for (int idx = tid; idx < 4096; idx += 256) {
        int p = idx >> 6, cm = idx & 63;
        B2t[cm * 65 + p] = g_B2[(pos0 << 6) + idx];
    }
    for (int idx = tid; idx < 9216; idx += 256) {
        int oc = idx >> 6, cm = idx & 63;
        ws[cm * 144 + oc] = w_out[idx];              // w_out[oc][cm]
    }
    __syncthreads();

    int pl = tid & 63, ocg = tid >> 6;               // ocg block of 36 oc
    u64 acc[18];
    #pragma unroll
    for (int j = 0; j < 18; j++) acc[j] = 0;

    for (int cm = 0; cm < 64; cm++) {
        u64 bv = dup2(B2t[cm * 65 + pl]);
        const ulonglong2* wp = (const ulonglong2*)&ws[cm * 144 + ocg * 36];
        #pragma unroll
        for (int j = 0; j < 9; j++) {
            ulonglong2 w = wp[j];
            fma2(acc[2 * j],     w.x, bv);
            fma2(acc[2 * j + 1], w.y, bv);
        }
    }

    int b = pos0 >> 12, hw0 = pos0 & 4095;
    float* op = out + (size_t)b * 589824 + hw0 + pl;
    #pragma unroll
    for (int j = 0; j < 18; j++) {
        int oc0 = ocg * 36 + 2 * j;
        float2 v = unpack2(acc[j]);
        op[(size_t)oc0 * 4096]       = v.x * g_sout[oc0]     + g_tout[oc0];
        op[(size_t)(oc0 + 1) * 4096] = v.y * g_sout[oc0 + 1] + g_tout[oc0 + 1];
    }
}

// ---------------- launch ----------------
extern "C" void kernel_launch(void* const* d_in, const int* in_sizes, int n_in,
                              void* d_out, int out_size)
{
    (void)in_sizes; (void)n_in; (void)out_size;
    const float* x     = (const float*)d_in[0];
    const float* w_in  = (const float*)d_in[1];
    const float* gin   = (const float*)d_in[2];
    const float* bin   = (const float*)d_in[3];
    const float* min_  = (const float*)d_in[4];
    const float* vin   = (const float*)d_in[5];
    const float* w1    = (const float*)d_in[6];
    const float* g1    = (const float*)d_in[7];
    const float* b1    = (const float*)d_in[8];
    const float* m1    = (const float*)d_in[9];
    const float* v1    = (const float*)d_in[10];
    const float* w2    = (const float*)d_in[11];
    const float* g2    = (const float*)d_in[12];
    const float* b2    = (const float*)d_in[13];
    const float* m2    = (const float*)d_in[14];
    const float* v2    = (const float*)d_in[15];
    const float* w_out = (const float*)d_in[16];
    const float* go    = (const float*)d_in[17];
    const float* bo    = (const float*)d_in[18];
    const float* mo    = (const float*)d_in[19];
    const float* vo    = (const float*)d_in[20];
    float* out = (float*)d_out;

    cudaFuncSetAttribute(gemm1_kernel,   cudaFuncAttributeMaxDynamicSharedMemorySize, 66816);
    cudaFuncSetAttribute(conv1_kernel,   cudaFuncAttributeMaxDynamicSharedMemorySize, 51456);
    cudaFuncSetAttribute(conv2_kernel,   cudaFuncAttributeMaxDynamicSharedMemorySize, 91136);
    cudaFuncSetAttribute(gemmout_kernel, cudaFuncAttributeMaxDynamicSharedMemorySize, 53504);

    prep_kernel<<<144, 256>>>(w_in, gin, bin, min_, vin,
                              w1, g1, b1, m1, v1,
                              w2, g2, b2, m2, v2,
                              go, bo, mo, vo);
    normalize_kernel<<<64, 256>>>(x);
    gemm1_kernel<<<4096, 256, 66816>>>();
    conv1_kernel<<<2048, 256, 51456>>>();
    conv2_kernel<<<512, 256, 91136>>>();
    gemmout_kernel<<<256, 256, 53504>>>(w_out, out);
}

// round 11
// speedup vs baseline: 1.6105x; 1.6105x over previous
#include <cuda_runtime.h>

#define EPS 1e-5f

typedef unsigned long long u64;

// ---------------- f32x2 helpers ----------------
__device__ __forceinline__ void fma2(u64& d, u64 a, u64 b) {
    asm volatile("fma.rn.f32x2 %0, %1, %2, %0;" : "+l"(d) : "l"(a), "l"(b));
}
__device__ __forceinline__ u64 dup2(float x) {
    u64 r; asm("mov.b64 %0, {%1, %1};" : "=l"(r) : "f"(x)); return r;
}
__device__ __forceinline__ float2 unpack2(u64 v) {
    float2 r; asm("mov.b64 {%0, %1}, %2;" : "=f"(r.x), "=f"(r.y) : "l"(v)); return r;
}

// ---------------- tf32 mma helpers ----------------
__device__ __forceinline__ float cvt_tf32(float x) {
    unsigned r; asm("cvt.rna.tf32.f32 %0, %1;" : "=r"(r) : "f"(x));
    return __uint_as_float(r);
}
__device__ __forceinline__ void mma_tf32(float* d, const unsigned* a, const unsigned* b) {
    asm volatile(
        "mma.sync.aligned.m16n8k8.row.col.f32.tf32.tf32.f32 "
        "{%0,%1,%2,%3}, {%4,%5,%6,%7}, {%8,%9}, {%0,%1,%2,%3};\n"
        : "+f"(d[0]), "+f"(d[1]), "+f"(d[2]), "+f"(d[3])
        : "r"(a[0]), "r"(a[1]), "r"(a[2]), "r"(a[3]), "r"(b[0]), "r"(b[1]));
}

// ---------------- scratch (device globals; no allocation allowed) ----------------
__device__ float g_xn[4 * 144 * 4096];        // normalized input
__device__ float g_wint[144 * 64];            // w_in transposed [c][o]
__device__ float g_w1oc[9 * 64 * 64];         // w1 as [drds][o][o2]
__device__ float g_w2tt[64 * 576];            // w2 as [o3][rs*64+o2]
__device__ float g_sin[64], g_tin[64];
__device__ float g_s1[64],  g_t1[64];
__device__ float g_s2[64],  g_t2[64];
__device__ float g_sout[144], g_tout[144];
__device__ float g_A[16384 * 25 * 64];        // post GEMM1+BN+ReLU  [pos][k][o]
__device__ float g_A1[16384 * 9 * 64];        // post conv1+BN+ReLU  [pos][rs][o2]
__device__ float g_B2[16384 * 64];            // post conv2+BN+ReLU  [pos][o3]

// ---------------- weight transpose + BN folding ----------------
__global__ void prep_kernel(const float* __restrict__ w_in,
                            const float* __restrict__ gin, const float* __restrict__ bin,
                            const float* __restrict__ min_, const float* __restrict__ vin,
                            const float* __restrict__ w1,
                            const float* __restrict__ g1, const float* __restrict__ b1,
                            const float* __restrict__ m1, const float* __restrict__ v1,
                            const float* __restrict__ w2,
                            const float* __restrict__ g2, const float* __restrict__ b2,
                            const float* __restrict__ m2, const float* __restrict__ v2,
                            const float* __restrict__ go, const float* __restrict__ bo,
                            const float* __restrict__ mo, const float* __restrict__ vo)
{
    int i = blockIdx.x * blockDim.x + threadIdx.x;   // grid covers 36864
    if (i < 36864) {
        // w1oc[drds][o][c] = w1[c][o][drds]   (c = output channel)
        int drds = i >> 12; int r1 = i & 4095;
        int o = r1 >> 6; int c = r1 & 63;
        g_w1oc[i] = w1[(c * 64 + o) * 9 + drds];
        // w2tt[o3][rs*64+o2] = w2[o3][o2][rs]
        int o3 = i / 576; int r2 = i - o3 * 576;
        int rs = r2 >> 6; int o2b = r2 & 63;
        g_w2tt[i] = w2[(o3 * 64 + o2b) * 9 + rs];
    }
    if (i < 9216) { int c = i >> 6; int o = i & 63; g_wint[i] = w_in[o * 144 + c]; }
    if (i < 64) {
        float s;
        s = gin[i] * rsqrtf(vin[i] + EPS); g_sin[i] = s; g_tin[i] = bin[i] - min_[i] * s;
        s = g1[i]  * rsqrtf(v1[i]  + EPS); g_s1[i]  = s; g_t1[i]  = b1[i]  - m1[i]  * s;
        s = g2[i]  * rsqrtf(v2[i]  + EPS); g_s2[i]  = s; g_t2[i]  = b2[i]  - m2[i]  * s;
    }
    if (i < 144) {
        float s = go[i] * rsqrtf(vo[i] + EPS); g_sout[i] = s; g_tout[i] = bo[i] - mo[i] * s;
    }
}

// ---------------- L2 normalize over channels ----------------
__global__ void normalize_kernel(const float* __restrict__ x)
{
    int p = blockIdx.x * 256 + threadIdx.x;          // 16384 positions
    int b = p >> 12, hw = p & 4095;
    const float* xb = x + (size_t)b * 589824 + hw;   // 144*4096
    float ss = 0.f;
    #pragma unroll 4
    for (int c = 0; c < 144; c++) { float v = xb[c * 4096]; ss += v * v; }
    float inv = 1.0f / fmaxf(sqrtf(ss), 1e-12f);
    float* yb = g_xn + (size_t)b * 589824 + hw;
    #pragma unroll 4
    for (int c = 0; c < 144; c++) yb[c * 4096] = xb[c * 4096] * inv;
}

// ---------------- GEMM1 (mirror-symmetric): only k=12..24 computed ----------------
// z[o,k,p] = sum_c w[o,c]*xn[c,p+dk]*xn[c,p]  is symmetric under
// (p,k) <-> (p+dk, 24-k); BN+ReLU elementwise => A[p][k] = A[p+dk][24-k].
__global__ void __launch_bounds__(256) gemm1_kernel()
{
    extern __shared__ float sm[];
    float* y   = sm;                                 // 7488
    float* wsm = sm + 7488;                          // 9216
    int pos0 = blockIdx.x << 2;
    int b = pos0 >> 12, hw0 = pos0 & 4095;
    int h0 = hw0 >> 6, w0 = hw0 & 63;
    int tid = threadIdx.x;
    const float* xb = g_xn + (size_t)b * 589824;

    // stage w_in^T  [c][o]
    #pragma unroll
    for (int j = 0; j < 9; j++) {
        int idx = tid + j * 256;                     // 2304 float4 = 9216 floats
        ((float4*)wsm)[idx] = ((const float4*)g_wint)[idx];
    }
    // build y tile for k=12..24: y[(c*13 + (k-12))*4 + p]
    for (int u = tid; u < 1872; u += 256) {
        int c = u / 13, kt = u - c * 13;
        int k = kt + 12;
        int kh = k / 5, kw = k - kh * 5;
        int gh = h0 + kh - 2;
        bool rok = ((unsigned)gh < 64u);
        const float* xc = xb + c * 4096;
        float4 out;
        float ctr0 = xc[(h0 << 6) + w0 + 0], ctr1 = xc[(h0 << 6) + w0 + 1];
        float ctr2 = xc[(h0 << 6) + w0 + 2], ctr3 = xc[(h0 << 6) + w0 + 3];
        int gw0 = w0 + kw - 2;
        float v0 = (rok && (unsigned)(gw0 + 0) < 64u) ? xc[(gh << 6) + gw0 + 0] : 0.f;
        float v1 = (rok && (unsigned)(gw0 + 1) < 64u) ? xc[(gh << 6) + gw0 + 1] : 0.f;
        float v2 = (rok && (unsigned)(gw0 + 2) < 64u) ? xc[(gh << 6) + gw0 + 2] : 0.f;
        float v3 = (rok && (unsigned)(gw0 + 3) < 64u) ? xc[(gh << 6) + gw0 + 3] : 0.f;
        out.x = v0 * ctr0; out.y = v1 * ctr1; out.z = v2 * ctr2; out.w = v3 * ctr3;
        ((float4*)y)[u] = out;
    }
    __syncthreads();

    int lane = tid & 31, g = tid >> 5;
    int oc = lane & 15;                              // channels 4oc..4oc+3
    int h  = lane >> 4;                              // c-parity half
    int nk = (g < 5) ? 2 : 1;                        // k = 12 + g + 8*kk
    u64 acc[2][4][2];                                // [kk][ch][pair]
    #pragma unroll
    for (int kk = 0; kk < 2; kk++)
        #pragma unroll
        for (int j = 0; j < 4; j++) { acc[kk][j][0] = 0; acc[kk][j][1] = 0; }

    const float* wrow = wsm + (h << 6) + (oc << 2);  // + ci*128
    const float* yrow = y + ((h * 13 + g) << 2);     // + ci*104, + kk*32

    #pragma unroll 2
    for (int ci = 0; ci < 72; ci++) {
        float4 w4 = *(const float4*)(wrow + (ci << 7));
        u64 wd0 = dup2(w4.x), wd1 = dup2(w4.y), wd2 = dup2(w4.z), wd3 = dup2(w4.w);
        const float* yc = yrow + ci * 104;
        #pragma unroll
        for (int kk = 0; kk < 2; kk++) {
            if (kk < nk) {
                ulonglong2 yv = *(const ulonglong2*)(yc + (kk << 5));
                fma2(acc[kk][0][0], yv.x, wd0); fma2(acc[kk][0][1], yv.y, wd0);
                fma2(acc[kk][1][0], yv.x, wd1); fma2(acc[kk][1][1], yv.y, wd1);
                fma2(acc[kk][2][0], yv.x, wd2); fma2(acc[kk][2][1], yv.y, wd2);
                fma2(acc[kk][3][0], yv.x, wd3); fma2(acc[kk][3][1], yv.y, wd3);
            }
        }
    }

    // epilogue: reduce across c-halves; write self slot, mirror-partner slot,
    // and the OOB-partner constant relu(t).
    float4 s4 = *(const float4*)&g_sin[oc << 2];
    float4 t4 = *(const float4*)&g_tin[oc << 2];
    float4 cst;
    cst.x = fmaxf(t4.x, 0.f); cst.y = fmaxf(t4.y, 0.f);
    cst.z = fmaxf(t4.z, 0.f); cst.w = fmaxf(t4.w, 0.f);

    #pragma unroll
    for (int kk = 0; kk < 2; kk++) {
        if (kk < nk) {
            int k = 12 + g + (kk << 3);
            float2 sel[4];
            #pragma unroll
            for (int j = 0; j < 4; j++) {
                u64 p0 = acc[kk][j][0], p1 = acc[kk][j][1];
                u64 q0 = __shfl_xor_sync(0xffffffffu, p0, 16);
                u64 q1 = __shfl_xor_sync(0xffffffffu, p1, 16);
                float2 a0 = unpack2(p0), b0 = unpack2(q0);
                float2 a1 = unpack2(p1), b1 = unpack2(q1);
                float2 s0 = make_float2(a0.x + b0.x, a0.y + b0.y);
                float2 s1 = make_float2(a1.x + b1.x, a1.y + b1.y);
                sel[j] = h ? s1 : s0;
            }
            float4 r[2];
            r[0].x = fmaxf(sel[0].x * s4.x + t4.x, 0.f);
            r[0].y = fmaxf(sel[1].x * s4.y + t4.y, 0.f);
            r[0].z = fmaxf(sel[2].x * s4.z + t4.z, 0.f);
            r[0].w = fmaxf(sel[3].x * s4.w + t4.w, 0.f);
            r[1].x = fmaxf(sel[0].y * s4.x + t4.x, 0.f);
            r[1].y = fmaxf(sel[1].y * s4.y + t4.y, 0.f);
            r[1].z = fmaxf(sel[2].y * s4.z + t4.z, 0.f);
            r[1].w = fmaxf(sel[3].y * s4.w + t4.w, 0.f);

            int kh = k / 5, kw = k - kh * 5;
            int dh = kh - 2, dw = kw - 2;
            int mk = 24 - k;
            #pragma unroll
            for (int e = 0; e < 2; e++) {
                int poff = (h << 1) + e;
                int p = pos0 + poff;
                *(float4*)&g_A[(((size_t)p * 25 + k) << 6) + (oc << 2)] = r[e];
                if (k != 12) {
                    int ww = w0 + poff;
                    int qh = h0 + dh, qw = ww + dw;
                    if ((unsigned)qh < 64u && (unsigned)qw < 64u) {
                        int q = (b << 12) + (qh << 6) + qw;
                        *(float4*)&g_A[(((size_t)q * 25 + mk) << 6) + (oc << 2)] = r[e];
                    }
                    int rh = h0 - dh, rw = ww - dw;
                    if (!((unsigned)rh < 64u && (unsigned)rw < 64u)) {
                        *(float4*)&g_A[(((size_t)p * 25 + mk) << 6) + (oc << 2)] = cst;
                    }
                }
            }
        }
    }
}

// ---------------- Conv1 as tf32 tensor-core GEMM ----------------
// A1[R][o2] = sum_{drds,o} g_A[p(R)][roff(rs(R))+shift(drds)][o] * w1oc[drds][o][o2]
// R = pos*9+rs (147456 rows). CTA = 128 rows; 9 K-slices of 64 (per drds).
// smem: As[128][68] (34.8KB) + ws[64][72] (18.4KB) = 53.2KB. tf32 cvt in staging.
// 8 warps: warp w owns m32n32 block (m0 = (w>>1)*32, n0 = (w&1)*32).
// Per k8-step: 8 A-LDS.32 (bank 4*row+t, conflict-free) + 8 B-LDS.32
// (bank 8*t+g, conflict-free) + 8 mma.m16n8k8.tf32.
__global__ void __launch_bounds__(256) conv1_kernel()
{
    extern __shared__ float sm[];
    float* As = sm;                                  // 128*68 = 8704
    float* ws = sm + 8704;                           // 64*72  = 4608
    int r0 = blockIdx.x << 7;
    int tid = threadIdx.x;
    int lane = tid & 31, w = tid >> 5;
    int g = lane >> 2, t = lane & 3;
    int m0 = (w >> 1) << 5;                          // 0,32,64,96
    int n0 = (w & 1) << 5;                           // 0,32

    float acc[2][4][4];
    #pragma unroll
    for (int i = 0; i < 2; i++)
        #pragma unroll
        for (int j = 0; j < 4; j++) {
            acc[i][j][0] = 0.f; acc[i][j][1] = 0.f;
            acc[i][j][2] = 0.f; acc[i][j][3] = 0.f;
        }

    for (int drds = 0; drds < 9; drds++) {
        int dr = drds / 3, ds = drds - dr * 3;
        int shift = dr * 5 + ds;
        __syncthreads();                             // prev mma reads done
        // stage A slice: rows r0..r0+127, k-cols = channel o of patch(rs,drds)
        #pragma unroll
        for (int j2 = 0; j2 < 8; j2++) {
            int idx = tid + (j2 << 8);               // 2048 float4
            int row = idx >> 4, cf = idx & 15;
            int R = r0 + row;
            int p = R / 9, rs = R - p * 9;
            int patch = rs + 2 * (rs / 3) + shift;
            float4 v = *(const float4*)(g_A + (((size_t)(p * 25 + patch)) << 6) + (cf << 2));
            float4 o;
            o.x = cvt_tf32(v.x); o.y = cvt_tf32(v.y);
            o.z = cvt_tf32(v.z); o.w = cvt_tf32(v.w);
            *(float4*)(As + row * 68 + (cf << 2)) = o;
        }
        // stage B slice: ws[o][o2]
        #pragma unroll
        for (int j2 = 0; j2 < 4; j2++) {
            int idx = tid + (j2 << 8);               // 1024 float4
            int row = idx >> 4, cf = idx & 15;
            float4 v = *(const float4*)(g_w1oc + (drds << 12) + (row << 6) + (cf << 2));
            float4 o;
            o.x = cvt_tf32(v.x); o.y = cvt_tf32(v.y);
            o.z = cvt_tf32(v.z); o.w = cvt_tf32(v.w);
            *(float4*)(ws + row * 72 + (cf << 2)) = o;
        }
        __syncthreads();

        #pragma unroll
        for (int kk = 0; kk < 8; kk++) {
            int ko = kk << 3;
            unsigned a[2][4], b[4][2];
            #pragma unroll
            for (int i = 0; i < 2; i++) {
                const float* ar = As + (m0 + (i << 4) + g) * 68 + ko + t;
                a[i][0] = __float_as_uint(ar[0]);
                a[i][1] = __float_as_uint(ar[8 * 68]);
                a[i][2] = __float_as_uint(ar[4]);
                a[i][3] = __float_as_uint(ar[8 * 68 + 4]);
            }
            #pragma unroll
            for (int j = 0; j < 4; j++) {
                const float* br = ws + (ko + t) * 72 + n0 + (j << 3) + g;
                b[j][0] = __float_as_uint(br[0]);
                b[j][1] = __float_as_uint(br[4 * 72]);
            }
            #pragma unroll
            for (int i = 0; i < 2; i++)
                #pragma unroll
                for (int j = 0; j < 4; j++)
                    mma_tf32(acc[i][j], a[i], b[j]);
        }
    }

    // epilogue: BN + ReLU, write g_A1[R][o2]
    #pragma unroll
    for (int i = 0; i < 2; i++) {
        size_t R = (size_t)r0 + m0 + (i << 4) + g;
        #pragma unroll
        for (int j = 0; j < 4; j++) {
            int col = n0 + (j << 3) + (t << 1);
            float2 s = *(const float2*)&g_s1[col];
            float2 tb = *(const float2*)&g_t1[col];
            float2 o0, o1;
            o0.x = fmaxf(acc[i][j][0] * s.x + tb.x, 0.f);
            o0.y = fmaxf(acc[i][j][1] * s.y + tb.y, 0.f);
            o1.x = fmaxf(acc[i][j][2] * s.x + tb.x, 0.f);
            o1.y = fmaxf(acc[i][j][3] * s.y + tb.y, 0.f);
            *(float2*)&g_A1[(R << 6) + col]       = o0;
            *(float2*)&g_A1[((R + 8) << 6) + col] = o1;
        }
    }
}

// ---------------- Conv2: 3x3 -> 1x1, 64->64; BN+ReLU ----------------
// CTA = 32 positions. smem: A1[32][576] (73.7KB) + w chunk [64][68] (17.4KB) -> 2 CTA/SM.
__global__ void __launch_bounds__(256) conv2_kernel()
{
    extern __shared__ float sm[];
    float* A1s = sm;                                 // 18432
    float* ws2 = sm + 18432;                         // 4352
    int pos0 = blockIdx.x << 5;
    int tid = threadIdx.x;

    const float4* src = (const float4*)(g_A1 + ((size_t)pos0 * 576));
    for (int i = tid; i < 4608; i += 256) ((float4*)A1s)[i] = src[i];

    int o3b = tid & 31, g = tid >> 5;                // warp g owns p = g+8i
    u64 acc[4][2];
    #pragma unroll
    for (int i = 0; i < 4; i++) { acc[i][0] = 0; acc[i][1] = 0; }

    for (int jc = 0; jc < 9; jc++) {
        __syncthreads();
        #pragma unroll
        for (int j2 = 0; j2 < 16; j2++) {
            int idx = tid + (j2 << 8);
            ws2[(idx >> 6) * 68 + (idx & 63)] = g_w2tt[(idx >> 6) * 576 + (jc << 6) + (idx & 63)];
        }
        __syncthreads();

        int jbase = jc << 6;
        for (int jj = 0; jj < 64; jj += 4) {
            ulonglong2 wlo = *(const ulonglong2*)&ws2[o3b * 68 + jj];
            ulonglong2 whi = *(const ulonglong2*)&ws2[(o3b + 32) * 68 + jj];
            #pragma unroll
            for (int i = 0; i < 4; i++) {
                int p = g + (i << 3);
                ulonglong2 a = *(const ulonglong2*)&A1s[p * 576 + jbase + jj];
                fma2(acc[i][0], a.x, wlo.x);
                fma2(acc[i][0], a.y, wlo.y);
                fma2(acc[i][1], a.x, whi.x);
                fma2(acc[i][1], a.y, whi.y);
            }
        }
    }

    float sa = g_s2[o3b], ta = g_t2[o3b], sb = g_s2[o3b + 32], tb = g_t2[o3b + 32];
    #pragma unroll
    for (int i = 0; i < 4; i++) {
        int p = pos0 + g + (i << 3);
        float2 va = unpack2(acc[i][0]);
        float2 vb = unpack2(acc[i][1]);
        g_B2[(p << 6) + o3b]      = fmaxf((va.x + va.y) * sa + ta, 0.f);
        g_B2[(p << 6) + o3b + 32] = fmaxf((vb.x + vb.y) * sb + tb, 0.f);
    }
}

// ---------------- GEMM out: 64->144, BN (no ReLU) ----------------
__global__ void __launch_bounds__(256) gemmout_kernel(const float* __restrict__ w_out,
                                                      float* __restrict__ out)
{
    extern __shared__ float sm[];                    // 4160 + 9216 floats
    float* B2t = sm;
    float* ws  = sm + 4160;
    int pos0 = blockIdx.x << 6;
    int tid = threadIdx.x;

    for (int idx = tid; idx < 4096; idx += 256) {
        int p = idx >> 6, cm = idx & 63;
        B2t[cm * 65 + p] = g_B2[(pos0 << 6) + idx];
    }
    for (int idx = tid; idx < 9216; idx += 256) {
        int oc = idx >> 6, cm = idx & 63;
        ws[cm * 144 + oc] = w_out[idx];              // w_out[oc][cm]
    }
    __syncthreads();

    int pl = tid & 63, ocg = tid >> 6;               // ocg block of 36 oc
    u64 acc[18];
    #pragma unroll
    for (int j = 0; j < 18; j++) acc[j] = 0;

    for (int cm = 0; cm < 64; cm++) {
        u64 bv = dup2(B2t[cm * 65 + pl]);
        const ulonglong2* wp = (const ulonglong2*)&ws[cm * 144 + ocg * 36];
        #pragma unroll
        for (int j = 0; j < 9; j++) {
            ulonglong2 w = wp[j];
            fma2(acc[2 * j],     w.x, bv);
            fma2(acc[2 * j + 1], w.y, bv);
        }
    }

    int b = pos0 >> 12, hw0 = pos0 & 4095;
    float* op = out + (size_t)b * 589824 + hw0 + pl;
    #pragma unroll
    for (int j = 0; j < 18; j++) {
        int oc0 = ocg * 36 + 2 * j;
        float2 v = unpack2(acc[j]);
        op[(size_t)oc0 * 4096]       = v.x * g_sout[oc0]     + g_tout[oc0];
        op[(size_t)(oc0 + 1) * 4096] = v.y * g_sout[oc0 + 1] + g_tout[oc0 + 1];
    }
}

// ---------------- launch ----------------
extern "C" void kernel_launch(void* const* d_in, const int* in_sizes, int n_in,
                              void* d_out, int out_size)
{
    (void)in_sizes; (void)n_in; (void)out_size;
    const float* x     = (const float*)d_in[0];
    const float* w_in  = (const float*)d_in[1];
    const float* gin   = (const float*)d_in[2];
    const float* bin   = (const float*)d_in[3];
    const float* min_  = (const float*)d_in[4];
    const float* vin   = (const float*)d_in[5];
    const float* w1    = (const float*)d_in[6];
    const float* g1    = (const float*)d_in[7];
    const float* b1    = (const float*)d_in[8];
    const float* m1    = (const float*)d_in[9];
    const float* v1    = (const float*)d_in[10];
    const float* w2    = (const float*)d_in[11];
    const float* g2    = (const float*)d_in[12];
    const float* b2    = (const float*)d_in[13];
    const float* m2    = (const float*)d_in[14];
    const float* v2    = (const float*)d_in[15];
    const float* w_out = (const float*)d_in[16];
    const float* go    = (const float*)d_in[17];
    const float* bo    = (const float*)d_in[18];
    const float* mo    = (const float*)d_in[19];
    const float* vo    = (const float*)d_in[20];
    float* out = (float*)d_out;

    cudaFuncSetAttribute(gemm1_kernel,   cudaFuncAttributeMaxDynamicSharedMemorySize, 66816);
    cudaFuncSetAttribute(conv1_kernel,   cudaFuncAttributeMaxDynamicSharedMemorySize, 53248);
    cudaFuncSetAttribute(conv2_kernel,   cudaFuncAttributeMaxDynamicSharedMemorySize, 91136);
    cudaFuncSetAttribute(gemmout_kernel, cudaFuncAttributeMaxDynamicSharedMemorySize, 53504);

    prep_kernel<<<144, 256>>>(w_in, gin, bin, min_, vin,
                              w1, g1, b1, m1, v1,
                              w2, g2, b2, m2, v2,
                              go, bo, mo, vo);
    normalize_kernel<<<64, 256>>>(x);
    gemm1_kernel<<<4096, 256, 66816>>>();
    conv1_kernel<<<1152, 256, 53248>>>();
    conv2_kernel<<<512, 256, 91136>>>();
    gemmout_kernel<<<256, 256, 53504>>>(w_out, out);
}

// round 15
// speedup vs baseline: 2.2385x; 1.3899x over previous
#include <cuda_runtime.h>

#define EPS 1e-5f

typedef unsigned long long u64;

// ---------------- f32x2 helpers ----------------
__device__ __forceinline__ void fma2(u64& d, u64 a, u64 b) {
    asm volatile("fma.rn.f32x2 %0, %1, %2, %0;" : "+l"(d) : "l"(a), "l"(b));
}
__device__ __forceinline__ u64 dup2(float x) {
    u64 r; asm("mov.b64 %0, {%1, %1};" : "=l"(r) : "f"(x)); return r;
}
__device__ __forceinline__ float2 unpack2(u64 v) {
    float2 r; asm("mov.b64 {%0, %1}, %2;" : "=f"(r.x), "=f"(r.y) : "l"(v)); return r;
}

// ---------------- tf32 mma helpers ----------------
__device__ __forceinline__ float cvt_tf32(float x) {
    unsigned r; asm("cvt.rna.tf32.f32 %0, %1;" : "=r"(r) : "f"(x));
    return __uint_as_float(r);
}
__device__ __forceinline__ void mma_tf32(float* d, const unsigned* a, const unsigned* b) {
    asm volatile(
        "mma.sync.aligned.m16n8k8.row.col.f32.tf32.tf32.f32 "
        "{%0,%1,%2,%3}, {%4,%5,%6,%7}, {%8,%9}, {%0,%1,%2,%3};\n"
        : "+f"(d[0]), "+f"(d[1]), "+f"(d[2]), "+f"(d[3])
        : "r"(a[0]), "r"(a[1]), "r"(a[2]), "r"(a[3]), "r"(b[0]), "r"(b[1]));
}

// ---------------- scratch (device globals; no allocation allowed) ----------------
__device__ float g_invn[16384];               // 1/||x|| per position
__device__ float g_xnt[16384 * 144];          // normalized input, position-major [pos][c]
__device__ float g_wint[144 * 64];            // w_in transposed [c][o]
__device__ float g_w1oc[9 * 64 * 64];         // w1 as [drds][o][o2]
__device__ float g_w2jt[576 * 64];            // w2 as [j = rs*64+o2][o3]
__device__ float g_sin[64], g_tin[64];
__device__ float g_s1[64],  g_t1[64];
__device__ float g_s2[64],  g_t2[64];
__device__ float g_sout[144], g_tout[144];
__device__ float g_A[16384 * 25 * 64];        // post GEMM1+BN+ReLU  [pos][k][o]
__device__ float g_A1[16384 * 9 * 64];        // post conv1+BN+ReLU  [pos][rs][o2]
__device__ float g_B2[16384 * 64];            // post conv2+BN+ReLU  [pos][o3]

// ---------------- weight transpose + BN folding ----------------
__global__ void prep_kernel(const float* __restrict__ w_in,
                            const float* __restrict__ gin, const float* __restrict__ bin,
                            const float* __restrict__ min_, const float* __restrict__ vin,
                            const float* __restrict__ w1,
                            const float* __restrict__ g1, const float* __restrict__ b1,
                            const float* __restrict__ m1, const float* __restrict__ v1,
                            const float* __restrict__ w2,
                            const float* __restrict__ g2, const float* __restrict__ b2,
                            const float* __restrict__ m2, const float* __restrict__ v2,
                            const float* __restrict__ go, const float* __restrict__ bo,
                            const float* __restrict__ mo, const float* __restrict__ vo)
{
    int i = blockIdx.x * blockDim.x + threadIdx.x;   // grid covers 36864
    if (i < 36864) {
        // w1oc[drds][o][c] = w1[c][o][drds]   (c = output channel)
        int drds = i >> 12; int r1 = i & 4095;
        int o = r1 >> 6; int c = r1 & 63;
        g_w1oc[i] = w1[(c * 64 + o) * 9 + drds];
        // w2jt[j][o3] = w2[o3][o2][rs],  j = rs*64+o2
        int j = i >> 6; int o3 = i & 63;
        int rs = j >> 6; int o2 = j & 63;
        g_w2jt[i] = w2[(o3 * 64 + o2) * 9 + rs];
    }
    if (i < 9216) { int c = i >> 6; int o = i & 63; g_wint[i] = w_in[o * 144 + c]; }
    if (i < 64) {
        float s;
        s = gin[i] * rsqrtf(vin[i] + EPS); g_sin[i] = s; g_tin[i] = bin[i] - min_[i] * s;
        s = g1[i]  * rsqrtf(v1[i]  + EPS); g_s1[i]  = s; g_t1[i]  = b1[i]  - m1[i]  * s;
        s = g2[i]  * rsqrtf(v2[i]  + EPS); g_s2[i]  = s; g_t2[i]  = b2[i]  - m2[i]  * s;
    }
    if (i < 144) {
        float s = go[i] * rsqrtf(vo[i] + EPS); g_sout[i] = s; g_tout[i] = bo[i] - mo[i] * s;
    }
}

// ---------------- inverse L2 norm per position ----------------
__global__ void invn_kernel(const float* __restrict__ x)
{
    int p = blockIdx.x * 256 + threadIdx.x;          // 16384 positions
    int b = p >> 12, hw = p & 4095;
    const float* xb = x + (size_t)b * 589824 + hw;   // 144*4096
    float ss = 0.f;
    #pragma unroll 4
    for (int c = 0; c < 144; c++) { float v = xb[c * 4096]; ss += v * v; }
    g_invn[p] = 1.0f / fmaxf(sqrtf(ss), 1e-12f);
}

// ---------------- transpose + normalize: g_xnt[pos][c] = x[c][pos] * invn[pos] ----------------
__global__ void xpose_kernel(const float* __restrict__ x)
{
    __shared__ float tile[32][33];
    int p0 = blockIdx.x << 5;
    int c0 = blockIdx.y << 5;
    int tx = threadIdx.x, ty = threadIdx.y;          // 32 x 8
    int b = p0 >> 12, hw0 = p0 & 4095;
    float inv = g_invn[p0 + tx];
    const float* xb = x + (size_t)b * 589824 + hw0 + tx;
    #pragma unroll
    for (int i = 0; i < 4; i++) {
        int c = c0 + ty + (i << 3);
        if (c < 144) tile[ty + (i << 3)][tx] = xb[c << 12] * inv;
    }
    __syncthreads();
    #pragma unroll
    for (int i = 0; i < 4; i++) {
        int p = p0 + ty + (i << 3);
        int c = c0 + tx;
        if (c < 144) g_xnt[p * 144 + c] = tile[tx][ty + (i << 3)];
    }
}

// ---------------- GEMM1 as tf32 mma (mirror-symmetric, k=12..24 only) ----------------
// rows R = pos_local*13 + kt (104 valid, padded to 112), K=144 (2 chunks of 72), N=64.
// As[112][76] (ld76: bank 12g+t conflict-free), Bs[72][72] (bank 8t+g conflict-free).
// 8 warps: warp w owns n0 = 8w, all 7 m16 tiles.
__global__ void __launch_bounds__(256) gemm1_kernel()
{
    extern __shared__ float sm[];
    float* As = sm;                                  // 112*76 = 8512
    float* Bs = sm + 8512;                           // 72*72  = 5184
    int pos0 = blockIdx.x << 3;                      // 8 positions
    int tid = threadIdx.x;
    int lane = tid & 31, w = tid >> 5;
    int g = lane >> 2, t = lane & 3;
    int n0 = w << 3;

    float acc[7][4];
    #pragma unroll
    for (int i = 0; i < 7; i++) {
        acc[i][0] = 0.f; acc[i][1] = 0.f; acc[i][2] = 0.f; acc[i][3] = 0.f;
    }

    for (int kc = 0; kc < 2; kc++) {
        __syncthreads();
        // stage As: y[r][c] = xnt[q][c] * xnt[p][c], tf32
        for (int idx = tid; idx < 2016; idx += 256) {        // 112*18 float4
            int r = idx / 18, cf = idx - r * 18;
            int c = kc * 72 + (cf << 2);
            float4 v = make_float4(0.f, 0.f, 0.f, 0.f);
            if (r < 104) {
                int pl = r / 13, kt = r - pl * 13;
                int p = pos0 + pl;
                int k = kt + 12;
                int kh = k / 5, kw = k - kh * 5;
                int hh = (p >> 6) & 63, ww = p & 63;
                int qh = hh + kh - 2, qw = ww + kw - 2;
                if ((unsigned)qh < 64u && (unsigned)qw < 64u) {
                    int q = (p & ~4095) + (qh << 6) + qw;
                    float4 pa = *(const float4*)&g_xnt[q * 144 + c];
                    float4 ce = *(const float4*)&g_xnt[p * 144 + c];
                    v.x = cvt_tf32(pa.x * ce.x);
                    v.y = cvt_tf32(pa.y * ce.y);
                    v.z = cvt_tf32(pa.z * ce.z);
                    v.w = cvt_tf32(pa.w * ce.w);
                }
            }
            *(float4*)&As[r * 76 + (cf << 2)] = v;
        }
        // stage Bs[c_local][o] from g_wint[c][o]
        for (int idx = tid; idx < 1152; idx += 256) {        // 72*16 float4
            int cl = idx >> 4, of = idx & 15;
            float4 v = *(const float4*)&g_wint[((kc * 72 + cl) << 6) + (of << 2)];
            v.x = cvt_tf32(v.x); v.y = cvt_tf32(v.y);
            v.z = cvt_tf32(v.z); v.w = cvt_tf32(v.w);
            *(float4*)&Bs[cl * 72 + (of << 2)] = v;
        }
        __syncthreads();

        #pragma unroll
        for (int kk = 0; kk < 9; kk++) {
            int ko = kk << 3;
            unsigned b2[2];
            b2[0] = __float_as_uint(Bs[(ko + t) * 72 + n0 + g]);
            b2[1] = __float_as_uint(Bs[(ko + t + 4) * 72 + n0 + g]);
            #pragma unroll
            for (int i = 0; i < 7; i++) {
                unsigned a[4];
                const float* ar = As + ((i << 4) + g) * 76 + ko + t;
                a[0] = __float_as_uint(ar[0]);
                a[1] = __float_as_uint(ar[8 * 76]);
                a[2] = __float_as_uint(ar[4]);
                a[3] = __float_as_uint(ar[8 * 76 + 4]);
                mma_tf32(acc[i], a, b2);
            }
        }
    }

    // epilogue: BN+ReLU; write self slot + mirror partner + OOB constant
    int col = n0 + (t << 1);
    float2 s2 = *(const float2*)&g_sin[col];
    float2 tb = *(const float2*)&g_tin[col];
    float2 cst = make_float2(fmaxf(tb.x, 0.f), fmaxf(tb.y, 0.f));

    #pragma unroll
    for (int i = 0; i < 7; i++) {
        #pragma unroll
        for (int e = 0; e < 2; e++) {
            int r = (i << 4) + g + (e << 3);
            if (r < 104) {
                int pl = r / 13, kt = r - pl * 13;
                int p = pos0 + pl;
                int k = kt + 12;
                float2 rv;
                rv.x = fmaxf(acc[i][(e << 1) + 0] * s2.x + tb.x, 0.f);
                rv.y = fmaxf(acc[i][(e << 1) + 1] * s2.y + tb.y, 0.f);
                *(float2*)&g_A[(((size_t)p * 25 + k) << 6) + col] = rv;
                if (k != 12) {
                    int kh = k / 5, kw = k - kh * 5;
                    int dh = kh - 2, dw = kw - 2;
                    int mk = 24 - k;
                    int hh = (p >> 6) & 63, ww = p & 63;
                    int qh = hh + dh, qw = ww + dw;
                    if ((unsigned)qh < 64u && (unsigned)qw < 64u) {
                        int q = (p & ~4095) + (qh << 6) + qw;
                        *(float2*)&g_A[(((size_t)q * 25 + mk) << 6) + col] = rv;
                    }
                    int rh = hh - dh, rw = ww - dw;
                    if (!((unsigned)rh < 64u && (unsigned)rw < 64u)) {
                        *(float2*)&g_A[(((size_t)p * 25 + mk) << 6) + col] = cst;
                    }
                }
            }
        }
    }
}

// ---------------- Conv1 as tf32 tensor-core GEMM (unchanged, passing) ----------------
__global__ void __launch_bounds__(256) conv1_kernel()
{
    extern __shared__ float sm[];
    float* As = sm;                                  // 128*68 = 8704
    float* ws = sm + 8704;                           // 64*72  = 4608
    int r0 = blockIdx.x << 7;
    int tid = threadIdx.x;
    int lane = tid & 31, w = tid >> 5;
    int g = lane >> 2, t = lane & 3;
    int m0 = (w >> 1) << 5;                          // 0,32,64,96
    int n0 = (w & 1) << 5;                           // 0,32

    float acc[2][4][4];
    #pragma unroll
    for (int i = 0; i < 2; i++)
        #pragma unroll
        for (int j = 0; j < 4; j++) {
            acc[i][j][0] = 0.f; acc[i][j][1] = 0.f;
            acc[i][j][2] = 0.f; acc[i][j][3] = 0.f;
        }

    for (int drds = 0; drds < 9; drds++) {
        int dr = drds / 3, ds = drds - dr * 3;
        int shift = dr * 5 + ds;
        __syncthreads();
        #pragma unroll
        for (int j2 = 0; j2 < 8; j2++) {
            int idx = tid + (j2 << 8);               // 2048 float4
            int row = idx >> 4, cf = idx & 15;
            int R = r0 + row;
            int p = R / 9, rs = R - p * 9;
            int patch = rs + 2 * (rs / 3) + shift;
            float4 v = *(const float4*)(g_A + (((size_t)(p * 25 + patch)) << 6) + (cf << 2));
            float4 o;
            o.x = cvt_tf32(v.x); o.y = cvt_tf32(v.y);
            o.z = cvt_tf32(v.z); o.w = cvt_tf32(v.w);
            *(float4*)(As + row * 68 + (cf << 2)) = o;
        }
        #pragma unroll
        for (int j2 = 0; j2 < 4; j2++) {
            int idx = tid + (j2 << 8);               // 1024 float4
            int row = idx >> 4, cf = idx & 15;
            float4 v = *(const float4*)(g_w1oc + (drds << 12) + (row << 6) + (cf << 2));
            float4 o;
            o.x = cvt_tf32(v.x); o.y = cvt_tf32(v.y);
            o.z = cvt_tf32(v.z); o.w = cvt_tf32(v.w);
            *(float4*)(ws + row * 72 + (cf << 2)) = o;
        }
        __syncthreads();

        #pragma unroll
        for (int kk = 0; kk < 8; kk++) {
            int ko = kk << 3;
            unsigned a[2][4], b[4][2];
            #pragma unroll
            for (int i = 0; i < 2; i++) {
                const float* ar = As + (m0 + (i << 4) + g) * 68 + ko + t;
                a[i][0] = __float_as_uint(ar[0]);
                a[i][1] = __float_as_uint(ar[8 * 68]);
                a[i][2] = __float_as_uint(ar[4]);
                a[i][3] = __float_as_uint(ar[8 * 68 + 4]);
            }
            #pragma unroll
            for (int j = 0; j < 4; j++) {
                const float* br = ws + (ko + t) * 72 + n0 + (j << 3) + g;
                b[j][0] = __float_as_uint(br[0]);
                b[j][1] = __float_as_uint(br[4 * 72]);
            }
            #pragma unroll
            for (int i = 0; i < 2; i++)
                #pragma unroll
                for (int j = 0; j < 4; j++)
                    mma_tf32(acc[i][j], a[i], b[j]);
        }
    }

    #pragma unroll
    for (int i = 0; i < 2; i++) {
        size_t R = (size_t)r0 + m0 + (i << 4) + g;
        #pragma unroll
        for (int j = 0; j < 4; j++) {
            int col = n0 + (j << 3) + (t << 1);
            float2 s = *(const float2*)&g_s1[col];
            float2 tb = *(const float2*)&g_t1[col];
            float2 o0, o1;
            o0.x = fmaxf(acc[i][j][0] * s.x + tb.x, 0.f);
            o0.y = fmaxf(acc[i][j][1] * s.y + tb.y, 0.f);
            o1.x = fmaxf(acc[i][j][2] * s.x + tb.x, 0.f);
            o1.y = fmaxf(acc[i][j][3] * s.y + tb.y, 0.f);
            *(float2*)&g_A1[(R << 6) + col]       = o0;
            *(float2*)&g_A1[((R + 8) << 6) + col] = o1;
        }
    }
}

// ---------------- Conv2 as tf32 mma: M=16384, K=576 (9 chunks), N=64 ----------------
// CTA = 64 positions; As[64][68] + Bs[64][72]; warp w: m0 = (w>>1)*16, n0 = (w&1)*32.
__global__ void __launch_bounds__(256) conv2_kernel()
{
    extern __shared__ float sm[];
    float* As = sm;                                  // 64*68 = 4352
    float* Bs = sm + 4352;                           // 64*72 = 4608
    int pos0 = blockIdx.x << 6;
    int tid = threadIdx.x;
    int lane = tid & 31, w = tid >> 5;
    int g = lane >> 2, t = lane & 3;
    int m0 = (w >> 1) << 4;                          // 0,16,32,48
    int n0 = (w & 1) << 5;                           // 0,32

    float acc[4][4];
    #pragma unroll
    for (int j = 0; j < 4; j++) {
        acc[j][0] = 0.f; acc[j][1] = 0.f; acc[j][2] = 0.f; acc[j][3] = 0.f;
    }

    for (int jc = 0; jc < 9; jc++) {
        __syncthreads();
        #pragma unroll
        for (int j2 = 0; j2 < 4; j2++) {
            int idx = tid + (j2 << 8);               // 1024 float4
            int row = idx >> 4, cf = idx & 15;
            float4 v = *(const float4*)&g_A1[(size_t)(pos0 + row) * 576 + (jc << 6) + (cf << 2)];
            float4 o;
            o.x = cvt_tf32(v.x); o.y = cvt_tf32(v.y);
            o.z = cvt_tf32(v.z); o.w = cvt_tf32(v.w);
            *(float4*)(As + row * 68 + (cf << 2)) = o;
        }
        #pragma unroll
        for (int j2 = 0; j2 < 4; j2++) {
            int idx = tid + (j2 << 8);               // 1024 float4
            int row = idx >> 4, cf = idx & 15;
            float4 v = *(const float4*)&g_w2jt[((jc << 6) + row) * 64 + (cf << 2)];
            float4 o;
            o.x = cvt_tf32(v.x); o.y = cvt_tf32(v.y);
            o.z = cvt_tf32(v.z); o.w = cvt_tf32(v.w);
            *(float4*)(Bs + row * 72 + (cf << 2)) = o;
        }
        __syncthreads();

        #pragma unroll
        for (int kk = 0; kk < 8; kk++) {
            int ko = kk << 3;
            unsigned a[4];
            const float* ar = As + (m0 + g) * 68 + ko + t;
            a[0] = __float_as_uint(ar[0]);
            a[1] = __float_as_uint(ar[8 * 68]);
            a[2] = __float_as_uint(ar[4]);
            a[3] = __float_as_uint(ar[8 * 68 + 4]);
            #pragma unroll
            for (int j = 0; j < 4; j++) {
                unsigned b[2];
                const float* br = Bs + (ko + t) * 72 + n0 + (j << 3) + g;
                b[0] = __float_as_uint(br[0]);
                b[1] = __float_as_uint(br[4 * 72]);
                mma_tf32(acc[j], a, b);
            }
        }
    }

    size_t R = (size_t)pos0 + m0 + g;
    #pragma unroll
    for (int j = 0; j < 4; j++) {
        int col = n0 + (j << 3) + (t << 1);
        float2 s = *(const float2*)&g_s2[col];
        float2 tb = *(const float2*)&g_t2[col];
        float2 o0, o1;
        o0.x = fmaxf(acc[j][0] * s.x + tb.x, 0.f);
        o0.y = fmaxf(acc[j][1] * s.y + tb.y, 0.f);
        o1.x = fmaxf(acc[j][2] * s.x + tb.x, 0.f);
        o1.y = fmaxf(acc[j][3] * s.y + tb.y, 0.f);
        *(float2*)&g_B2[(R << 6) + col]       = o0;
        *(float2*)&g_B2[((R + 8) << 6) + col] = o1;
    }
}

// ---------------- GEMM out: 64->144, BN (no ReLU) ----------------
__global__ void __launch_bounds__(256) gemmout_kernel(const float* __restrict__ w_out,
                                                      float* __restrict__ out)
{
    extern __shared__ float sm[];                    // 4160 + 9216 floats
    float* B2t = sm;
    float* ws  = sm + 4160;
    int pos0 = blockIdx.x << 6;
    int tid = threadIdx.x;

    for (int idx = tid; idx < 4096; idx += 256) {
        int p = idx >> 6, cm = idx & 63;
        B2t[cm * 65 + p] = g_B2[(pos0 << 6) + idx];
    }
    for (int idx = tid; idx < 9216; idx += 256) {
        int oc = idx >> 6, cm = idx & 63;
        ws[cm * 144 + oc] = w_out[idx];              // w_out[oc][cm]
    }
    __syncthreads();

    int pl = tid & 63, ocg = tid >> 6;               // ocg block of 36 oc
    u64 acc[18];
    #pragma unroll
    for (int j = 0; j < 18; j++) acc[j] = 0;

    for (int cm = 0; cm < 64; cm++) {
        u64 bv = dup2(B2t[cm * 65 + pl]);
        const ulonglong2* wp = (const ulonglong2*)&ws[cm * 144 + ocg * 36];
        #pragma unroll
        for (int j = 0; j < 9; j++) {
            ulonglong2 w = wp[j];
            fma2(acc[2 * j],     w.x, bv);
            fma2(acc[2 * j + 1], w.y, bv);
        }
    }

    int b = pos0 >> 12, hw0 = pos0 & 4095;
    float* op = out + (size_t)b * 589824 + hw0 + pl;
    #pragma unroll
    for (int j = 0; j < 18; j++) {
        int oc0 = ocg * 36 + 2 * j;
        float2 v = unpack2(acc[j]);
        op[(size_t)oc0 * 4096]       = v.x * g_sout[oc0]     + g_tout[oc0];
        op[(size_t)(oc0 + 1) * 4096] = v.y * g_sout[oc0 + 1] + g_tout[oc0 + 1];
    }
}

// ---------------- launch ----------------
extern "C" void kernel_launch(void* const* d_in, const int* in_sizes, int n_in,
                              void* d_out, int out_size)
{
    (void)in_sizes; (void)n_in; (void)out_size;
    const float* x     = (const float*)d_in[0];
    const float* w_in  = (const float*)d_in[1];
    const float* gin   = (const float*)d_in[2];
    const float* bin   = (const float*)d_in[3];
    const float* min_  = (const float*)d_in[4];
    const float* vin   = (const float*)d_in[5];
    const float* w1    = (const float*)d_in[6];
    const float* g1    = (const float*)d_in[7];
    const float* b1    = (const float*)d_in[8];
    const float* m1    = (const float*)d_in[9];
    const float* v1    = (const float*)d_in[10];
    const float* w2    = (const float*)d_in[11];
    const float* g2    = (const float*)d_in[12];
    const float* b2    = (const float*)d_in[13];
    const float* m2    = (const float*)d_in[14];
    const float* v2    = (const float*)d_in[15];
    const float* w_out = (const float*)d_in[16];
    const float* go    = (const float*)d_in[17];
    const float* bo    = (const float*)d_in[18];
    const float* mo    = (const float*)d_in[19];
    const float* vo    = (const float*)d_in[20];
    float* out = (float*)d_out;

    cudaFuncSetAttribute(gemm1_kernel,   cudaFuncAttributeMaxDynamicSharedMemorySize, 54784);
    cudaFuncSetAttribute(conv1_kernel,   cudaFuncAttributeMaxDynamicSharedMemorySize, 53248);
    cudaFuncSetAttribute(conv2_kernel,   cudaFuncAttributeMaxDynamicSharedMemorySize, 35840);
    cudaFuncSetAttribute(gemmout_kernel, cudaFuncAttributeMaxDynamicSharedMemorySize, 53504);

    prep_kernel<<<144, 256>>>(w_in, gin, bin, min_, vin,
                              w1, g1, b1, m1, v1,
                              w2, g2, b2, m2, v2,
                              go, bo, mo, vo);
    invn_kernel<<<64, 256>>>(x);
    xpose_kernel<<<dim3(512, 5), dim3(32, 8)>>>(x);
    gemm1_kernel<<<2048, 256, 54784>>>();
    conv1_kernel<<<1152, 256, 53248>>>();
    conv2_kernel<<<256, 256, 35840>>>();
    gemmout_kernel<<<256, 256, 53504>>>(w_out, out);
}